// round 14
// baseline (speedup 1.0000x reference)
#include <cuda_runtime.h>
#include <cuda_bf16.h>
#include <cstdint>

#define DI __device__ __forceinline__

// ===================== static scratch (no runtime alloc) =====================
__device__ __nv_bfloat16 d_A1h[256 * 2048];
__device__ __nv_bfloat16 d_A1l[256 * 2048];
__device__ __nv_bfloat16 d_Bt1h[6144u * 2048u];
__device__ __nv_bfloat16 d_Bt1l[6144u * 2048u];
__device__ __nv_bfloat16 d_Bch[3u * 2048u * 2048u];
__device__ __nv_bfloat16 d_Bcl[3u * 2048u * 2048u];
__device__ __nv_bfloat16 d_k1h[256 * 6144];
__device__ __nv_bfloat16 d_k1l[256 * 6144];
__device__ float d_p1[3u * 256u * 6144u];   // stage1 K-split partials
__device__ float d_p2[9u * 256u * 6144u];   // stage2 tap x kseg partials
__device__ float d_g[64 * 6144];
__device__ float d_part[32 * 64 * 200];
__device__ float d_cls[64 * 200];
__device__ float d_norms[264];

// ===================== PTX helpers =====================
DI uint32_t smem_u32(const void* p) {
    uint32_t a;
    asm("{ .reg .u64 t; cvta.to.shared.u64 t, %1; cvt.u32.u64 %0, t; }" : "=r"(a) : "l"(p));
    return a;
}
DI void cp16(uint32_t dst, const void* src) {
    asm volatile("cp.async.cg.shared.global [%0], [%1], 16;" :: "r"(dst), "l"(src) : "memory");
}
DI void cp_commit() { asm volatile("cp.async.commit_group;" ::: "memory"); }
DI void cp_wait1()  { asm volatile("cp.async.wait_group 1;" ::: "memory"); }
DI void cp_wait0()  { asm volatile("cp.async.wait_group 0;" ::: "memory"); }

DI void ldsm4(uint32_t* r, uint32_t addr) {
    asm volatile("ldmatrix.sync.aligned.m8n8.x4.shared.b16 {%0,%1,%2,%3}, [%4];"
        : "=r"(r[0]), "=r"(r[1]), "=r"(r[2]), "=r"(r[3]) : "r"(addr));
}

// m16n8k16 bf16 mma, fp32 accum
DI void mma_bf16(float* c, const uint32_t* a, uint32_t b0, uint32_t b1) {
    asm volatile(
        "mma.sync.aligned.m16n8k16.row.col.f32.bf16.bf16.f32 "
        "{%0,%1,%2,%3}, {%4,%5,%6,%7}, {%8,%9}, {%0,%1,%2,%3};"
        : "+f"(c[0]), "+f"(c[1]), "+f"(c[2]), "+f"(c[3])
        : "r"(a[0]), "r"(a[1]), "r"(a[2]), "r"(a[3]), "r"(b0), "r"(b1));
}

DI float wredsum(float v) {
#pragma unroll
    for (int o = 16; o > 0; o >>= 1) v += __shfl_xor_sync(0xffffffffu, v, o);
    return v;
}

// ===================== prep kernels =====================
// merged prep: blocks [0,2048) do A1 split; blocks [2048,14336) do Bt1 permute+split
__global__ void prep_AB(const float* __restrict__ mem_feat, const float* __restrict__ wt) {
    __shared__ float s[32][97];
    const int bx = blockIdx.x;
    if (bx < 2048) {
        const int idx = bx * 256 + threadIdx.x;
        const int row = idx >> 11;
        float x = (row < 200) ? mem_feat[(size_t)row * 2048 + (idx & 2047)] : 0.f;
        __nv_bfloat16 h = __float2bfloat16(x);
        d_A1h[idx] = h;
        d_A1l[idx] = __float2bfloat16(x - __bfloat162float(h));
        return;
    }
    const int t = bx - 2048;
    const int m0 = (t % 192) * 32;
    const int i0 = (t / 192) * 32;
    const int p = m0 >> 11;
    const int o0 = m0 & 2047;
    const float* src = wt + (size_t)i0 * 6144 + (size_t)o0 * 3;
    for (int v = threadIdx.x; v < 768; v += 256) {
        int ii = v / 24, c4 = v % 24;
        float4 val = *reinterpret_cast<const float4*>(src + (size_t)ii * 6144 + c4 * 4);
        s[ii][c4 * 4 + 0] = val.x; s[ii][c4 * 4 + 1] = val.y;
        s[ii][c4 * 4 + 2] = val.z; s[ii][c4 * 4 + 3] = val.w;
    }
    __syncthreads();
    for (int v = threadIdx.x; v < 1024; v += 256) {
        int ml = v >> 5, il = v & 31;
        float x = s[il][ml * 3 + p];
        __nv_bfloat16 h = __float2bfloat16(x);
        size_t idx = (size_t)(m0 + ml) * 2048 + i0 + il;
        d_Bt1h[idx] = h;
        d_Bt1l[idx] = __float2bfloat16(x - __bfloat162float(h));
    }
}

// prep_Bc v2: coalesced float4 reads via smem, bf16x2 packed stores.
__global__ void prep_Bc(const float* __restrict__ wc) {
    __shared__ float s[1536];
    const size_t base = (size_t)blockIdx.x * 512u;
    const int tid = threadIdx.x;
    const float4* src = reinterpret_cast<const float4*>(wc + base * 3u);
    for (int t = tid; t < 384; t += 256)
        reinterpret_cast<float4*>(s)[t] = src[t];
    __syncthreads();
    const int i2 = tid * 2;
#pragma unroll
    for (int q = 0; q < 3; q++) {
        const float xa = s[i2 * 3 + q];
        const float xb = s[i2 * 3 + 3 + q];
        __nv_bfloat162 h2, l2;
        h2.x = __float2bfloat16(xa);
        h2.y = __float2bfloat16(xb);
        l2.x = __float2bfloat16(xa - __bfloat162float(h2.x));
        l2.y = __float2bfloat16(xb - __bfloat162float(h2.y));
        const size_t di = (size_t)q * 4194304u + base + i2;
        *reinterpret_cast<__nv_bfloat162*>(&d_Bch[di]) = h2;
        *reinterpret_cast<__nv_bfloat162*>(&d_Bcl[di]) = l2;
    }
}

// g_kernel v2: float4 loads
__global__ void g_kernel(const float* __restrict__ feat, const float* __restrict__ w_sp) {
    __shared__ float ws[200];
    const int tid = threadIdx.x;
    if (tid < 198) {
        float v = 0.f;
        if (tid >= 1 && tid <= 196) v = w_sp[tid - 1];
        ws[tid] = v;
    }
    __syncthreads();
    const int w = blockIdx.x * 8 + (tid >> 5);
    const int lane = tid & 31;
    const int b = w >> 11;
    const int c = w & 2047;
    const float4* x4 = reinterpret_cast<const float4*>(
        feat + ((size_t)b * 2048 + c) * 196);

    float4 v0 = x4[lane];
    float4 v1 = make_float4(0.f, 0.f, 0.f, 0.f);
    if (lane < 17) v1 = x4[32 + lane];

    float a0 = 0.f, a1 = 0.f, a2 = 0.f;
    {
        const int t = lane * 4;
        const float* e = &v0.x;
#pragma unroll
        for (int k = 0; k < 4; k++) {
            a0 = fmaf(e[k], ws[t + k + 2], a0);
            a1 = fmaf(e[k], ws[t + k + 1], a1);
            a2 = fmaf(e[k], ws[t + k],     a2);
        }
    }
    if (lane < 17) {
        const int t = 128 + lane * 4;
        const float* e = &v1.x;
#pragma unroll
        for (int k = 0; k < 4; k++) {
            a0 = fmaf(e[k], ws[t + k + 2], a0);
            a1 = fmaf(e[k], ws[t + k + 1], a1);
            a2 = fmaf(e[k], ws[t + k],     a2);
        }
    }
    a0 = wredsum(a0); a1 = wredsum(a1); a2 = wredsum(a2);
    if (lane == 0) {
        d_g[(size_t)b * 6144 + c]        = a0;
        d_g[(size_t)b * 6144 + 2048 + c] = a1;
        d_g[(size_t)b * 6144 + 4096 + c] = a2;
    }
}

// ===================== HMMA tap-GEMM: 128x128 tile, K-split(3), 512 threads =====================
// M partition: y=0 -> rows [0,112) (7 frags), y=1 -> rows [112,208) (6 frags).
// y is the INNER block index (bx&1) so y-pairs are co-resident and share B tiles in L2.
static constexpr int SMEM_BYTES = 3 * 65536 + 1024;

DI uint32_t swz(int r, int g) {
    return ((uint32_t)r << 7) + (((uint32_t)(g ^ (r & 7))) << 4);
}

// mode 0 (stage1): C-partial = A1@Bt1^T over kseg -> d_p1[kseg]
// mode 1 (stage2): C-partial = k1@Bc^T over (tap,kseg) -> d_p2[s*3+kseg]
__global__ void __launch_bounds__(512, 1)
gemm_tap(const __nv_bfloat16* __restrict__ Ah, const __nv_bfloat16* __restrict__ Al, int lda,
         const __nv_bfloat16* __restrict__ Bh, const __nv_bfloat16* __restrict__ Bl,
         int mode)
{
    extern __shared__ char dsm[];

    const int tid = threadIdx.x;
    const int yb = blockIdx.x & 1;             // inner: y-pairs co-resident
    const int bx = blockIdx.x >> 1;
    const int m0 = yb * 112;                   // 0 or 112
    const int MLIM = yb ? 208 : 112;           // valid-row limit for this tile
    const int ALIM = MLIM - m0;                // 112 (y=0) / 96 (y=1) local valid rows

    size_t aBase, bBase;
    int outcol, slot, kseg;
    float* outbuf;
    if (mode == 0) {
        kseg = bx / 48;
        const int colu = bx % 48;
        aBase = 0;
        bBase = (size_t)colu * 128u * 2048u;
        outcol = colu * 128;
        slot = kseg;
        outbuf = d_p1;
    } else {
        kseg = bx / 112;
        const int u = bx % 112;
        const int tap = u >> 4;
        const int ct = u & 15;
        int p, s, j, q;
        if (tap < 2)      { p = 0; s = tap;     j = tap;   q = tap + 1; }
        else if (tap < 5) { p = 1; s = tap - 2; j = s;     q = s; }
        else              { p = 2; s = tap - 5; j = s + 1; q = s; }
        aBase = (size_t)j * 2048u;
        bBase = (size_t)q * 4194304u + (size_t)(ct * 128) * 2048u;
        outcol = p * 2048 + ct * 128;
        slot = s * 3 + kseg;
        outbuf = d_p2;
    }
    const int kstart = (kseg == 0) ? 0 : (kseg == 1 ? 11 : 22);
    const int nch = (kseg < 2) ? 11 : 10;

    const uint32_t dsm_u = smem_u32(dsm);
    const uint32_t dbase = (dsm_u + 1023u) & ~1023u;

    // loader geometry: 4 threads/row, 2 x 16B groups per operand each
    const int lrow = tid >> 2;
    const int gq = (tid & 3) << 1;
    const bool aLoad = (lrow < ALIM);          // skip A rows never read by ldsm
    const size_t aRowB = (size_t)(m0 + lrow) * lda + aBase;
    const size_t bRowB = bBase + (size_t)lrow * 2048u;

    // compute geometry: 16 warps as 4(m) x 4(n); warp tile 32x32
    const int lane = tid & 31;
    const int warp = tid >> 5;
    const int m0w = (warp >> 2) * 32;
    const int n0w = (warp & 3) * 32;
    const int lr = lane & 15;
    const int kb = lane >> 4;

    const int rem = MLIM - m0 - m0w;
    const int nfragw = (rem <= 0) ? 0 : (rem >= 32 ? 2 : 1);

    float acc[2][4][4];
#pragma unroll
    for (int t = 0; t < 2; t++)
#pragma unroll
        for (int n = 0; n < 4; n++)
#pragma unroll
            for (int j = 0; j < 4; j++) acc[t][n][j] = 0.f;

#define LOADC(cc, bb) do { \
    const int _kc = (kstart + (cc)) << 6; \
    const uint32_t _b0 = dbase + (uint32_t)(bb) * 65536u; \
    const __nv_bfloat16* _ah = Ah + aRowB + _kc; \
    const __nv_bfloat16* _al = Al + aRowB + _kc; \
    const __nv_bfloat16* _bh = Bh + bRowB + _kc; \
    const __nv_bfloat16* _bl = Bl + bRowB + _kc; \
    _Pragma("unroll") \
    for (int _j = 0; _j < 2; _j++) { \
        const int _g = gq + _j; \
        const uint32_t _o = swz(lrow, _g); \
        if (aLoad) { \
            cp16(_b0 + _o,           _ah + _g * 8); \
            cp16(_b0 + 16384u + _o,  _al + _g * 8); \
        } \
        cp16(_b0 + 32768u + _o,  _bh + _g * 8); \
        cp16(_b0 + 49152u + _o,  _bl + _g * 8); \
    } \
    cp_commit(); \
} while (0)

    LOADC(0, 0);
    LOADC(1, 1);

    for (int c = 0; c < nch; ++c) {
        if (c < nch - 1) cp_wait1(); else cp_wait0();
        __syncthreads();
        if (c + 2 < nch) LOADC(c + 2, (c + 2) % 3);

        const uint32_t bb = dbase + (uint32_t)(c % 3) * 65536u;
        const uint32_t sAh = bb, sAl = bb + 16384u, sBh = bb + 32768u, sBl = bb + 49152u;

        if (nfragw > 0) {
#pragma unroll
            for (int kk = 0; kk < 4; kk++) {
                const int gk = (kk << 1) | kb;

                uint32_t ah[2][4], al[2][4], bhf[2][4], blf[2][4];
#pragma unroll
                for (int t = 0; t < 2; t++) {
                    if (t < nfragw) {
                        const uint32_t off = swz(m0w + t * 16 + lr, gk);
                        ldsm4(ah[t], sAh + off);
                        ldsm4(al[t], sAl + off);
                    }
                }
#pragma unroll
                for (int n = 0; n < 2; n++) {
                    const uint32_t off = swz(n0w + n * 16 + lr, gk);
                    ldsm4(bhf[n], sBh + off);
                    ldsm4(blf[n], sBl + off);
                }

#pragma unroll
                for (int t = 0; t < 2; t++)
                    if (t < nfragw)
#pragma unroll
                        for (int n = 0; n < 2; n++) {
                            mma_bf16(acc[t][2 * n],     ah[t], bhf[n][0], bhf[n][2]);
                            mma_bf16(acc[t][2 * n + 1], ah[t], bhf[n][1], bhf[n][3]);
                        }
#pragma unroll
                for (int t = 0; t < 2; t++)
                    if (t < nfragw)
#pragma unroll
                        for (int n = 0; n < 2; n++) {
                            mma_bf16(acc[t][2 * n],     al[t], bhf[n][0], bhf[n][2]);
                            mma_bf16(acc[t][2 * n + 1], al[t], bhf[n][1], bhf[n][3]);
                        }
#pragma unroll
                for (int t = 0; t < 2; t++)
                    if (t < nfragw)
#pragma unroll
                        for (int n = 0; n < 2; n++) {
                            mma_bf16(acc[t][2 * n],     ah[t], blf[n][0], blf[n][2]);
                            mma_bf16(acc[t][2 * n + 1], ah[t], blf[n][1], blf[n][3]);
                        }
            }
        }
    }
#undef LOADC

    // ---- epilogue: raw fp32 partials ----
    const int mrow = lane >> 2;
    const int npair = 2 * (lane & 3);
#pragma unroll
    for (int t = 0; t < 2; t++) {
        if (t >= nfragw) continue;
#pragma unroll
        for (int nt = 0; nt < 4; nt++) {
            const int nloc = n0w + nt * 8 + npair;
            const int mA = m0 + m0w + t * 16 + mrow;
            const size_t base = (size_t)slot * 1572864u + (size_t)mA * 6144 + outcol + nloc;
            *reinterpret_cast<float2*>(outbuf + base) =
                make_float2(acc[t][nt][0], acc[t][nt][1]);
            *reinterpret_cast<float2*>(outbuf + base + 8u * 6144u) =
                make_float2(acc[t][nt][2], acc[t][nt][3]);
        }
    }
}

// ===================== epi1: k1 = relu(sum p1 + bt) -> bf16 hi/lo =====================
__global__ void epi1(const float* __restrict__ bt) {
    const int idx = blockIdx.x * 256 + threadIdx.x;   // over 208*1536 float4s
    if (idx >= 208 * 1536) return;
    const int m = idx / 1536;
    const int c4 = idx - m * 1536;
    const int col = c4 * 4;
    const int o = col & 2047;
    const float4* P = reinterpret_cast<const float4*>(d_p1);
    const size_t o4 = (size_t)m * 1536 + c4;
    float4 v0 = P[o4];
    float4 v1 = P[393216u + o4];
    float4 v2 = P[786432u + o4];
    const float4 vb = *reinterpret_cast<const float4*>(bt + o);
    float r[4];
    r[0] = fmaxf(v0.x + v1.x + v2.x + vb.x, 0.f);
    r[1] = fmaxf(v0.y + v1.y + v2.y + vb.y, 0.f);
    r[2] = fmaxf(v0.z + v1.z + v2.z + vb.z, 0.f);
    r[3] = fmaxf(v0.w + v1.w + v2.w + vb.w, 0.f);
    __nv_bfloat16 h[4], l[4];
#pragma unroll
    for (int j = 0; j < 4; j++) {
        h[j] = __float2bfloat16(r[j]);
        l[j] = __float2bfloat16(r[j] - __bfloat162float(h[j]));
    }
    const size_t di = (size_t)m * 6144 + col;
    *reinterpret_cast<uint2*>(d_k1h + di) = *reinterpret_cast<uint2*>(h);
    *reinterpret_cast<uint2*>(d_k1l + di) = *reinterpret_cast<uint2*>(l);
}

// ===================== stage 3: cls = g . k2^T + b_sp (split-K, k2 built on the fly) =====================
__global__ void __launch_bounds__(256)
kernel_D(const float* __restrict__ g, const float* __restrict__ bc) {
    __shared__ __align__(16) float As[16][68];
    __shared__ __align__(16) float Bs[16][36];
    const int n0 = blockIdx.x * 32;
    const int ksplit = blockIdx.y;
    const int tid = threadIdx.x;
    const int tn = tid & 31;
    const int tg = tid >> 5;
    float acc[8];
#pragma unroll
    for (int j = 0; j < 8; j++) acc[j] = 0.f;
    const int kbase = ksplit * 192;
    const float4* P = reinterpret_cast<const float4*>(d_p2);
    for (int kc = 0; kc < 192; kc += 16) {
        const int k0 = kbase + kc;
        {
            int r = tid >> 2, kq = (tid & 3) * 4;
            float4 v = *reinterpret_cast<const float4*>(g + (size_t)r * 6144 + k0 + kq);
            As[kq + 0][r] = v.x; As[kq + 1][r] = v.y; As[kq + 2][r] = v.z; As[kq + 3][r] = v.w;
        }
        if (tid < 128) {
            int n = tid >> 2, kq = (tid & 3) * 4;
            int gn = n0 + n;
            float4 r4 = make_float4(0.f, 0.f, 0.f, 0.f);
            if (gn < 200) {
                const int col = k0 + kq;
                const int p = col >> 11;
                const int o = col & 2047;
                const size_t o4 = ((size_t)gn * 6144 + col) >> 2;
                const int nsl = (p == 1) ? 9 : 6;
                float rx = 0.f, ry = 0.f, rz = 0.f, rw = 0.f;
                for (int sl = 0; sl < nsl; sl++) {
                    float4 sv = P[(size_t)sl * 393216u + o4];
                    rx += sv.x; ry += sv.y; rz += sv.z; rw += sv.w;
                }
                const float4 vb = *reinterpret_cast<const float4*>(bc + o);
                r4.x = fmaxf(rx + vb.x, 0.f);
                r4.y = fmaxf(ry + vb.y, 0.f);
                r4.z = fmaxf(rz + vb.z, 0.f);
                r4.w = fmaxf(rw + vb.w, 0.f);
            }
            Bs[kq + 0][n] = r4.x; Bs[kq + 1][n] = r4.y; Bs[kq + 2][n] = r4.z; Bs[kq + 3][n] = r4.w;
        }
        __syncthreads();
#pragma unroll
        for (int k = 0; k < 16; k++) {
            float bv = Bs[k][tn];
            float a[8];
            *reinterpret_cast<float4*>(&a[0]) = *reinterpret_cast<const float4*>(&As[k][tg * 8]);
            *reinterpret_cast<float4*>(&a[4]) = *reinterpret_cast<const float4*>(&As[k][tg * 8 + 4]);
#pragma unroll
            for (int j = 0; j < 8; j++) acc[j] = fmaf(a[j], bv, acc[j]);
        }
        __syncthreads();
    }
    const int gn = n0 + tn;
    if (gn < 200) {
#pragma unroll
        for (int j = 0; j < 8; j++)
            d_part[((size_t)ksplit * 64 + tg * 8 + j) * 200 + gn] = acc[j];
    }
}

// reduce partials -> cls, fused cls-row norms (one block per b)
__global__ void __launch_bounds__(224)
reduce_D(const float* __restrict__ b_sp) {
    __shared__ float red[8];
    const int b = blockIdx.x;
    const int j = threadIdx.x;
    float s = 0.f;
    if (j < 200) {
        s = b_sp[0];
#pragma unroll
        for (int ks = 0; ks < 32; ks++) s += d_part[((size_t)ks * 64 + b) * 200 + j];
        d_cls[b * 200 + j] = s;
    }
    float sq = (j < 200) ? s * s : 0.f;
    sq = wredsum(sq);
    if ((j & 31) == 0) red[j >> 5] = sq;
    __syncthreads();
    if (j < 32) {
        float v = (j < 7) ? red[j] : 0.f;
        v = wredsum(v);
        if (j == 0) d_norms[b] = rsqrtf(v);
    }
}

// w_cls row norms (independent -> side stream)
__global__ void norms_w(const float* __restrict__ wcls) {
    const int w = (blockIdx.x * blockDim.x + threadIdx.x) >> 5;
    const int lane = threadIdx.x & 31;
    if (w >= 200) return;
    const float* row = wcls + (size_t)w * 200;
    float s = 0.f;
    for (int t = lane; t < 200; t += 32) { float x = row[t]; s = fmaf(x, x, s); }
    s = wredsum(s);
    if (lane == 0) d_norms[64 + w] = rsqrtf(s);
}

__global__ void cos_kernel(const float* __restrict__ wcls, const int* __restrict__ label,
                           float* __restrict__ out) {
    const int w = (blockIdx.x * blockDim.x + threadIdx.x) >> 5;
    const int lane = threadIdx.x & 31;
    if (w >= 12800) return;
    const int b = w / 200, c = w % 200;
    float s = 0.f;
    for (int t = lane; t < 200; t += 32)
        s = fmaf(d_cls[b * 200 + t], wcls[(size_t)c * 200 + t], s);
    s = wredsum(s);
    if (lane == 0) {
        float cosv = s * d_norms[b] * d_norms[64 + c];
        float m = (label[b] == c) ? 0.5f : 0.f;
        out[b * 200 + c] = 30.f * (cosv - m);
    }
}

// ===================== launch =====================
extern "C" void kernel_launch(void* const* d_in, const int* in_sizes, int n_in,
                              void* d_out, int out_size) {
    const float* feat     = (const float*)d_in[0];
    const int*   label    = (const int*)  d_in[1];
    const float* mem_feat = (const float*)d_in[2];
    const float* wt       = (const float*)d_in[3];
    const float* bt       = (const float*)d_in[4];
    const float* wc       = (const float*)d_in[5];
    const float* bc       = (const float*)d_in[6];
    const float* w_sp     = (const float*)d_in[7];
    const float* b_sp     = (const float*)d_in[8];
    const float* w_cls    = (const float*)d_in[9];
    float* out = (float*)d_out;

    cudaFuncSetAttribute(gemm_tap, cudaFuncAttributeMaxDynamicSharedMemorySize, SMEM_BYTES);

    __nv_bfloat16 *A1h, *A1l, *Bt1h, *Bt1l, *Bch, *Bcl, *k1h, *k1l;
    float *g;
    cudaGetSymbolAddress((void**)&A1h,  d_A1h);
    cudaGetSymbolAddress((void**)&A1l,  d_A1l);
    cudaGetSymbolAddress((void**)&Bt1h, d_Bt1h);
    cudaGetSymbolAddress((void**)&Bt1l, d_Bt1l);
    cudaGetSymbolAddress((void**)&Bch,  d_Bch);
    cudaGetSymbolAddress((void**)&Bcl,  d_Bcl);
    cudaGetSymbolAddress((void**)&k1h,  d_k1h);
    cudaGetSymbolAddress((void**)&k1l,  d_k1l);
    cudaGetSymbolAddress((void**)&g,    d_g);

    // side stream (captured fork/join): prep_Bc gates stage2; g/norms gate kernel_D
    cudaStream_t s2;
    cudaStreamCreateWithFlags(&s2, cudaStreamNonBlocking);
    cudaEvent_t ev0, ev2, ev3;
    cudaEventCreateWithFlags(&ev0, cudaEventDisableTiming);
    cudaEventCreateWithFlags(&ev2, cudaEventDisableTiming);
    cudaEventCreateWithFlags(&ev3, cudaEventDisableTiming);

    cudaEventRecord(ev0, 0);
    cudaStreamWaitEvent(s2, ev0, 0);
    prep_Bc<<<8192, 256, 0, s2>>>(wc);
    cudaEventRecord(ev2, s2);
    g_kernel<<<16384, 256, 0, s2>>>(feat, w_sp);
    norms_w<<<25, 256, 0, s2>>>(w_cls);
    cudaEventRecord(ev3, s2);

    // main branch: merged stage1 prep + stage1 GEMM (288 units, y-inner) + epi1
    prep_AB<<<14336, 256>>>(mem_feat, wt);
    gemm_tap<<<288, 512, SMEM_BYTES>>>(A1h, A1l, 2048, Bt1h, Bt1l, 0);
    epi1<<<1248, 256>>>(bt);

    // join prep_Bc before stage2
    cudaStreamWaitEvent(0, ev2, 0);
    // stage 2: 672 units (tap x kseg, y-inner) -> fp32 partials
    gemm_tap<<<672, 512, SMEM_BYTES>>>(k1h, k1l, 6144, Bch, Bcl, 1);

    // join g/norms before kernel_D
    cudaStreamWaitEvent(0, ev3, 0);
    kernel_D<<<dim3(7, 32), 256>>>(g, bc);
    reduce_D<<<64, 224>>>(b_sp);
    cos_kernel<<<1600, 256>>>(w_cls, label, out);

    (void)in_sizes; (void)n_in; (void)out_size;
}

// round 15
// speedup vs baseline: 1.0125x; 1.0125x over previous
#include <cuda_runtime.h>
#include <cuda_bf16.h>
#include <cstdint>

#define DI __device__ __forceinline__

// ===================== static scratch (no runtime alloc) =====================
__device__ __nv_bfloat16 d_A1h[256 * 2048];
__device__ __nv_bfloat16 d_A1l[256 * 2048];
__device__ __nv_bfloat16 d_Bt1h[6144u * 2048u];
__device__ __nv_bfloat16 d_Bt1l[6144u * 2048u];
__device__ __nv_bfloat16 d_Bch[3u * 2048u * 2048u];
__device__ __nv_bfloat16 d_Bcl[3u * 2048u * 2048u];
__device__ __nv_bfloat16 d_k1h[256 * 6144];
__device__ __nv_bfloat16 d_k1l[256 * 6144];
__device__ float d_p1[3u * 256u * 6144u];   // stage1 K-split partials
__device__ float d_p2[9u * 256u * 6144u];   // stage2 tap x kseg partials
__device__ float d_g[64 * 6144];
__device__ float d_part[32 * 64 * 200];
__device__ float d_cls[64 * 200];
__device__ float d_norms[264];

// ===================== PTX helpers =====================
DI uint32_t smem_u32(const void* p) {
    uint32_t a;
    asm("{ .reg .u64 t; cvta.to.shared.u64 t, %1; cvt.u32.u64 %0, t; }" : "=r"(a) : "l"(p));
    return a;
}
DI void cp16(uint32_t dst, const void* src) {
    asm volatile("cp.async.cg.shared.global [%0], [%1], 16;" :: "r"(dst), "l"(src) : "memory");
}
DI void cp_commit() { asm volatile("cp.async.commit_group;" ::: "memory"); }
DI void cp_wait1()  { asm volatile("cp.async.wait_group 1;" ::: "memory"); }
DI void cp_wait0()  { asm volatile("cp.async.wait_group 0;" ::: "memory"); }

DI void ldsm4(uint32_t* r, uint32_t addr) {
    asm volatile("ldmatrix.sync.aligned.m8n8.x4.shared.b16 {%0,%1,%2,%3}, [%4];"
        : "=r"(r[0]), "=r"(r[1]), "=r"(r[2]), "=r"(r[3]) : "r"(addr));
}

// m16n8k16 bf16 mma, fp32 accum
DI void mma_bf16(float* c, const uint32_t* a, uint32_t b0, uint32_t b1) {
    asm volatile(
        "mma.sync.aligned.m16n8k16.row.col.f32.bf16.bf16.f32 "
        "{%0,%1,%2,%3}, {%4,%5,%6,%7}, {%8,%9}, {%0,%1,%2,%3};"
        : "+f"(c[0]), "+f"(c[1]), "+f"(c[2]), "+f"(c[3])
        : "r"(a[0]), "r"(a[1]), "r"(a[2]), "r"(a[3]), "r"(b0), "r"(b1));
}

DI float wredsum(float v) {
#pragma unroll
    for (int o = 16; o > 0; o >>= 1) v += __shfl_xor_sync(0xffffffffu, v, o);
    return v;
}

// ===================== prep kernels =====================
__global__ void prep_A1(const float* __restrict__ mem_feat) {
    int idx = blockIdx.x * 256 + threadIdx.x;
    if (idx >= 256 * 2048) return;
    int row = idx >> 11;
    float x = (row < 200) ? mem_feat[(size_t)row * 2048 + (idx & 2047)] : 0.f;
    __nv_bfloat16 h = __float2bfloat16(x);
    d_A1h[idx] = h;
    d_A1l[idx] = __float2bfloat16(x - __bfloat162float(h));
}

// Bt1[m][i] = wt[i][(m&2047)*3 + (m>>11)]
__global__ void prep_Bt1(const float* __restrict__ wt) {
    __shared__ float s[32][97];
    const int m0 = blockIdx.x * 32;
    const int i0 = blockIdx.y * 32;
    const int p = m0 >> 11;
    const int o0 = m0 & 2047;
    const float* src = wt + (size_t)i0 * 6144 + (size_t)o0 * 3;
    for (int v = threadIdx.x; v < 768; v += 256) {
        int ii = v / 24, c4 = v % 24;
        float4 val = *reinterpret_cast<const float4*>(src + (size_t)ii * 6144 + c4 * 4);
        s[ii][c4 * 4 + 0] = val.x; s[ii][c4 * 4 + 1] = val.y;
        s[ii][c4 * 4 + 2] = val.z; s[ii][c4 * 4 + 3] = val.w;
    }
    __syncthreads();
    for (int v = threadIdx.x; v < 1024; v += 256) {
        int ml = v >> 5, il = v & 31;
        float x = s[il][ml * 3 + p];
        __nv_bfloat16 h = __float2bfloat16(x);
        size_t idx = (size_t)(m0 + ml) * 2048 + i0 + il;
        d_Bt1h[idx] = h;
        d_Bt1l[idx] = __float2bfloat16(x - __bfloat162float(h));
    }
}

// prep_Bc v2: coalesced float4 reads via smem, bf16x2 packed stores.
__global__ void prep_Bc(const float* __restrict__ wc) {
    __shared__ float s[1536];
    const size_t base = (size_t)blockIdx.x * 512u;
    const int tid = threadIdx.x;
    const float4* src = reinterpret_cast<const float4*>(wc + base * 3u);
    for (int t = tid; t < 384; t += 256)
        reinterpret_cast<float4*>(s)[t] = src[t];
    __syncthreads();
    const int i2 = tid * 2;
#pragma unroll
    for (int q = 0; q < 3; q++) {
        const float xa = s[i2 * 3 + q];
        const float xb = s[i2 * 3 + 3 + q];
        __nv_bfloat162 h2, l2;
        h2.x = __float2bfloat16(xa);
        h2.y = __float2bfloat16(xb);
        l2.x = __float2bfloat16(xa - __bfloat162float(h2.x));
        l2.y = __float2bfloat16(xb - __bfloat162float(h2.y));
        const size_t di = (size_t)q * 4194304u + base + i2;
        *reinterpret_cast<__nv_bfloat162*>(&d_Bch[di]) = h2;
        *reinterpret_cast<__nv_bfloat162*>(&d_Bcl[di]) = l2;
    }
}

// g_kernel v2: float4 loads
__global__ void g_kernel(const float* __restrict__ feat, const float* __restrict__ w_sp) {
    __shared__ float ws[200];
    const int tid = threadIdx.x;
    if (tid < 198) {
        float v = 0.f;
        if (tid >= 1 && tid <= 196) v = w_sp[tid - 1];
        ws[tid] = v;
    }
    __syncthreads();
    const int w = blockIdx.x * 8 + (tid >> 5);
    const int lane = tid & 31;
    const int b = w >> 11;
    const int c = w & 2047;
    const float4* x4 = reinterpret_cast<const float4*>(
        feat + ((size_t)b * 2048 + c) * 196);

    float4 v0 = x4[lane];
    float4 v1 = make_float4(0.f, 0.f, 0.f, 0.f);
    if (lane < 17) v1 = x4[32 + lane];

    float a0 = 0.f, a1 = 0.f, a2 = 0.f;
    {
        const int t = lane * 4;
        const float* e = &v0.x;
#pragma unroll
        for (int k = 0; k < 4; k++) {
            a0 = fmaf(e[k], ws[t + k + 2], a0);
            a1 = fmaf(e[k], ws[t + k + 1], a1);
            a2 = fmaf(e[k], ws[t + k],     a2);
        }
    }
    if (lane < 17) {
        const int t = 128 + lane * 4;
        const float* e = &v1.x;
#pragma unroll
        for (int k = 0; k < 4; k++) {
            a0 = fmaf(e[k], ws[t + k + 2], a0);
            a1 = fmaf(e[k], ws[t + k + 1], a1);
            a2 = fmaf(e[k], ws[t + k],     a2);
        }
    }
    a0 = wredsum(a0); a1 = wredsum(a1); a2 = wredsum(a2);
    if (lane == 0) {
        d_g[(size_t)b * 6144 + c]        = a0;
        d_g[(size_t)b * 6144 + 2048 + c] = a1;
        d_g[(size_t)b * 6144 + 4096 + c] = a2;
    }
}

// ===================== HMMA tap-GEMM: 128x128 tile, K-split(3), 512 threads =====================
static constexpr int SMEM_BYTES = 3 * 65536 + 1024;
static constexpr int MVALID = 208;

DI uint32_t swz(int r, int g) {
    return ((uint32_t)r << 7) + (((uint32_t)(g ^ (r & 7))) << 4);
}

// mode 0 (stage1): C-partial = A1@Bt1^T over kseg -> d_p1[kseg]
// mode 1 (stage2): C-partial = k1@Bc^T over (tap,kseg) -> d_p2[s*3+kseg]
__global__ void __launch_bounds__(512, 1)
gemm_tap(const __nv_bfloat16* __restrict__ Ah, const __nv_bfloat16* __restrict__ Al, int lda,
         const __nv_bfloat16* __restrict__ Bh, const __nv_bfloat16* __restrict__ Bl,
         int mode)
{
    extern __shared__ char dsm[];

    const int tid = threadIdx.x;
    const int bx = blockIdx.x;
    const int m0 = blockIdx.y * 128;

    size_t aBase, bBase;
    int outcol, slot, kseg;
    float* outbuf;
    if (mode == 0) {
        kseg = bx / 48;
        const int colu = bx % 48;
        aBase = 0;
        bBase = (size_t)colu * 128u * 2048u;
        outcol = colu * 128;
        slot = kseg;
        outbuf = d_p1;
    } else {
        kseg = bx / 112;
        const int u = bx % 112;
        const int tap = u >> 4;
        const int ct = u & 15;
        int p, s, j, q;
        if (tap < 2)      { p = 0; s = tap;     j = tap;   q = tap + 1; }
        else if (tap < 5) { p = 1; s = tap - 2; j = s;     q = s; }
        else              { p = 2; s = tap - 5; j = s + 1; q = s; }
        aBase = (size_t)j * 2048u;
        bBase = (size_t)q * 4194304u + (size_t)(ct * 128) * 2048u;
        outcol = p * 2048 + ct * 128;
        slot = s * 3 + kseg;
        outbuf = d_p2;
    }
    const int kstart = (kseg == 0) ? 0 : (kseg == 1 ? 11 : 22);
    const int nch = (kseg < 2) ? 11 : 10;

    const uint32_t dsm_u = smem_u32(dsm);
    const uint32_t dbase = (dsm_u + 1023u) & ~1023u;

    // loader geometry: 4 threads/row, 2 x 16B groups per operand each
    const int lrow = tid >> 2;
    const int gq = (tid & 3) << 1;
    const size_t aRowB = (size_t)(m0 + lrow) * lda + aBase;
    const size_t bRowB = bBase + (size_t)lrow * 2048u;

    // compute geometry: 16 warps as 4(m) x 4(n); warp tile 32x32
    const int lane = tid & 31;
    const int warp = tid >> 5;
    const int m0w = (warp >> 2) * 32;
    const int n0w = (warp & 3) * 32;
    const int lr = lane & 15;
    const int kb = lane >> 4;

    const int rem = MVALID - m0 - m0w;
    const int nfragw = (rem <= 0) ? 0 : (rem >= 32 ? 2 : 1);

    float acc[2][4][4];
#pragma unroll
    for (int t = 0; t < 2; t++)
#pragma unroll
        for (int n = 0; n < 4; n++)
#pragma unroll
            for (int j = 0; j < 4; j++) acc[t][n][j] = 0.f;

#define LOADC(cc, bb) do { \
    const int _kc = (kstart + (cc)) << 6; \
    const uint32_t _b0 = dbase + (uint32_t)(bb) * 65536u; \
    const __nv_bfloat16* _ah = Ah + aRowB + _kc; \
    const __nv_bfloat16* _al = Al + aRowB + _kc; \
    const __nv_bfloat16* _bh = Bh + bRowB + _kc; \
    const __nv_bfloat16* _bl = Bl + bRowB + _kc; \
    _Pragma("unroll") \
    for (int _j = 0; _j < 2; _j++) { \
        const int _g = gq + _j; \
        const uint32_t _o = swz(lrow, _g); \
        cp16(_b0 + _o,           _ah + _g * 8); \
        cp16(_b0 + 16384u + _o,  _al + _g * 8); \
        cp16(_b0 + 32768u + _o,  _bh + _g * 8); \
        cp16(_b0 + 49152u + _o,  _bl + _g * 8); \
    } \
    cp_commit(); \
} while (0)

    LOADC(0, 0);
    LOADC(1, 1);

    for (int c = 0; c < nch; ++c) {
        if (c < nch - 1) cp_wait1(); else cp_wait0();
        __syncthreads();
        if (c + 2 < nch) LOADC(c + 2, (c + 2) % 3);

        const uint32_t bb = dbase + (uint32_t)(c % 3) * 65536u;
        const uint32_t sAh = bb, sAl = bb + 16384u, sBh = bb + 32768u, sBl = bb + 49152u;

        if (nfragw > 0) {
#pragma unroll
            for (int kk = 0; kk < 4; kk++) {
                const int gk = (kk << 1) | kb;

                uint32_t ah[2][4], al[2][4], bhf[2][4], blf[2][4];
#pragma unroll
                for (int t = 0; t < 2; t++) {
                    if (t < nfragw) {
                        const uint32_t off = swz(m0w + t * 16 + lr, gk);
                        ldsm4(ah[t], sAh + off);
                        ldsm4(al[t], sAl + off);
                    }
                }
#pragma unroll
                for (int n = 0; n < 2; n++) {
                    const uint32_t off = swz(n0w + n * 16 + lr, gk);
                    ldsm4(bhf[n], sBh + off);
                    ldsm4(blf[n], sBl + off);
                }

#pragma unroll
                for (int t = 0; t < 2; t++)
                    if (t < nfragw)
#pragma unroll
                        for (int n = 0; n < 2; n++) {
                            mma_bf16(acc[t][2 * n],     ah[t], bhf[n][0], bhf[n][2]);
                            mma_bf16(acc[t][2 * n + 1], ah[t], bhf[n][1], bhf[n][3]);
                        }
#pragma unroll
                for (int t = 0; t < 2; t++)
                    if (t < nfragw)
#pragma unroll
                        for (int n = 0; n < 2; n++) {
                            mma_bf16(acc[t][2 * n],     al[t], bhf[n][0], bhf[n][2]);
                            mma_bf16(acc[t][2 * n + 1], al[t], bhf[n][1], bhf[n][3]);
                        }
#pragma unroll
                for (int t = 0; t < 2; t++)
                    if (t < nfragw)
#pragma unroll
                        for (int n = 0; n < 2; n++) {
                            mma_bf16(acc[t][2 * n],     ah[t], blf[n][0], blf[n][2]);
                            mma_bf16(acc[t][2 * n + 1], ah[t], blf[n][1], blf[n][3]);
                        }
            }
        }
    }
#undef LOADC

    // ---- epilogue: raw fp32 partials ----
    const int mrow = lane >> 2;
    const int npair = 2 * (lane & 3);
#pragma unroll
    for (int t = 0; t < 2; t++) {
        if (t >= nfragw) continue;
#pragma unroll
        for (int nt = 0; nt < 4; nt++) {
            const int nloc = n0w + nt * 8 + npair;
            const int mA = m0 + m0w + t * 16 + mrow;
            const size_t base = (size_t)slot * 1572864u + (size_t)mA * 6144 + outcol + nloc;
            *reinterpret_cast<float2*>(outbuf + base) =
                make_float2(acc[t][nt][0], acc[t][nt][1]);
            *reinterpret_cast<float2*>(outbuf + base + 8u * 6144u) =
                make_float2(acc[t][nt][2], acc[t][nt][3]);
        }
    }
}

// ===================== epi1: k1 = relu(sum p1 + bt) -> bf16 hi/lo =====================
__global__ void epi1(const float* __restrict__ bt) {
    const int idx = blockIdx.x * 256 + threadIdx.x;   // over 208*1536 float4s
    if (idx >= 208 * 1536) return;
    const int m = idx / 1536;
    const int c4 = idx - m * 1536;
    const int col = c4 * 4;
    const int o = col & 2047;
    const float4* P = reinterpret_cast<const float4*>(d_p1);
    const size_t o4 = (size_t)m * 1536 + c4;
    float4 v0 = P[o4];
    float4 v1 = P[393216u + o4];
    float4 v2 = P[786432u + o4];
    const float4 vb = *reinterpret_cast<const float4*>(bt + o);
    float r[4];
    r[0] = fmaxf(v0.x + v1.x + v2.x + vb.x, 0.f);
    r[1] = fmaxf(v0.y + v1.y + v2.y + vb.y, 0.f);
    r[2] = fmaxf(v0.z + v1.z + v2.z + vb.z, 0.f);
    r[3] = fmaxf(v0.w + v1.w + v2.w + vb.w, 0.f);
    __nv_bfloat16 h[4], l[4];
#pragma unroll
    for (int j = 0; j < 4; j++) {
        h[j] = __float2bfloat16(r[j]);
        l[j] = __float2bfloat16(r[j] - __bfloat162float(h[j]));
    }
    const size_t di = (size_t)m * 6144 + col;
    *reinterpret_cast<uint2*>(d_k1h + di) = *reinterpret_cast<uint2*>(h);
    *reinterpret_cast<uint2*>(d_k1l + di) = *reinterpret_cast<uint2*>(l);
}

// ===================== stage 3: cls = g . k2^T + b_sp (split-K, k2 built on the fly) =====================
__global__ void __launch_bounds__(256)
kernel_D(const float* __restrict__ g, const float* __restrict__ bc) {
    __shared__ __align__(16) float As[16][68];
    __shared__ __align__(16) float Bs[16][36];
    const int n0 = blockIdx.x * 32;
    const int ksplit = blockIdx.y;
    const int tid = threadIdx.x;
    const int tn = tid & 31;
    const int tg = tid >> 5;
    float acc[8];
#pragma unroll
    for (int j = 0; j < 8; j++) acc[j] = 0.f;
    const int kbase = ksplit * 192;
    const float4* P = reinterpret_cast<const float4*>(d_p2);
    for (int kc = 0; kc < 192; kc += 16) {
        const int k0 = kbase + kc;
        {
            int r = tid >> 2, kq = (tid & 3) * 4;
            float4 v = *reinterpret_cast<const float4*>(g + (size_t)r * 6144 + k0 + kq);
            As[kq + 0][r] = v.x; As[kq + 1][r] = v.y; As[kq + 2][r] = v.z; As[kq + 3][r] = v.w;
        }
        if (tid < 128) {
            int n = tid >> 2, kq = (tid & 3) * 4;
            int gn = n0 + n;
            float4 r4 = make_float4(0.f, 0.f, 0.f, 0.f);
            if (gn < 200) {
                const int col = k0 + kq;
                const int p = col >> 11;
                const int o = col & 2047;
                const size_t o4 = ((size_t)gn * 6144 + col) >> 2;
                const int nsl = (p == 1) ? 9 : 6;
                float rx = 0.f, ry = 0.f, rz = 0.f, rw = 0.f;
                for (int sl = 0; sl < nsl; sl++) {
                    float4 sv = P[(size_t)sl * 393216u + o4];
                    rx += sv.x; ry += sv.y; rz += sv.z; rw += sv.w;
                }
                const float4 vb = *reinterpret_cast<const float4*>(bc + o);
                r4.x = fmaxf(rx + vb.x, 0.f);
                r4.y = fmaxf(ry + vb.y, 0.f);
                r4.z = fmaxf(rz + vb.z, 0.f);
                r4.w = fmaxf(rw + vb.w, 0.f);
            }
            Bs[kq + 0][n] = r4.x; Bs[kq + 1][n] = r4.y; Bs[kq + 2][n] = r4.z; Bs[kq + 3][n] = r4.w;
        }
        __syncthreads();
#pragma unroll
        for (int k = 0; k < 16; k++) {
            float bv = Bs[k][tn];
            float a[8];
            *reinterpret_cast<float4*>(&a[0]) = *reinterpret_cast<const float4*>(&As[k][tg * 8]);
            *reinterpret_cast<float4*>(&a[4]) = *reinterpret_cast<const float4*>(&As[k][tg * 8 + 4]);
#pragma unroll
            for (int j = 0; j < 8; j++) acc[j] = fmaf(a[j], bv, acc[j]);
        }
        __syncthreads();
    }
    const int gn = n0 + tn;
    if (gn < 200) {
#pragma unroll
        for (int j = 0; j < 8; j++)
            d_part[((size_t)ksplit * 64 + tg * 8 + j) * 200 + gn] = acc[j];
    }
}

// reduce partials -> cls, fused cls-row norms (one block per b)
__global__ void __launch_bounds__(224)
reduce_D(const float* __restrict__ b_sp) {
    __shared__ float red[8];
    const int b = blockIdx.x;
    const int j = threadIdx.x;
    float s = 0.f;
    if (j < 200) {
        s = b_sp[0];
#pragma unroll
        for (int ks = 0; ks < 32; ks++) s += d_part[((size_t)ks * 64 + b) * 200 + j];
        d_cls[b * 200 + j] = s;
    }
    float sq = (j < 200) ? s * s : 0.f;
    sq = wredsum(sq);
    if ((j & 31) == 0) red[j >> 5] = sq;
    __syncthreads();
    if (j < 32) {
        float v = (j < 7) ? red[j] : 0.f;
        v = wredsum(v);
        if (j == 0) d_norms[b] = rsqrtf(v);
    }
}

// w_cls row norms (independent -> side stream)
__global__ void norms_w(const float* __restrict__ wcls) {
    const int w = (blockIdx.x * blockDim.x + threadIdx.x) >> 5;
    const int lane = threadIdx.x & 31;
    if (w >= 200) return;
    const float* row = wcls + (size_t)w * 200;
    float s = 0.f;
    for (int t = lane; t < 200; t += 32) { float x = row[t]; s = fmaf(x, x, s); }
    s = wredsum(s);
    if (lane == 0) d_norms[64 + w] = rsqrtf(s);
}

__global__ void cos_kernel(const float* __restrict__ wcls, const int* __restrict__ label,
                           float* __restrict__ out) {
    const int w = (blockIdx.x * blockDim.x + threadIdx.x) >> 5;
    const int lane = threadIdx.x & 31;
    if (w >= 12800) return;
    const int b = w / 200, c = w % 200;
    float s = 0.f;
    for (int t = lane; t < 200; t += 32)
        s = fmaf(d_cls[b * 200 + t], wcls[(size_t)c * 200 + t], s);
    s = wredsum(s);
    if (lane == 0) {
        float cosv = s * d_norms[b] * d_norms[64 + c];
        float m = (label[b] == c) ? 0.5f : 0.f;
        out[b * 200 + c] = 30.f * (cosv - m);
    }
}

// ===================== launch =====================
extern "C" void kernel_launch(void* const* d_in, const int* in_sizes, int n_in,
                              void* d_out, int out_size) {
    const float* feat     = (const float*)d_in[0];
    const int*   label    = (const int*)  d_in[1];
    const float* mem_feat = (const float*)d_in[2];
    const float* wt       = (const float*)d_in[3];
    const float* bt       = (const float*)d_in[4];
    const float* wc       = (const float*)d_in[5];
    const float* bc       = (const float*)d_in[6];
    const float* w_sp     = (const float*)d_in[7];
    const float* b_sp     = (const float*)d_in[8];
    const float* w_cls    = (const float*)d_in[9];
    float* out = (float*)d_out;

    cudaFuncSetAttribute(gemm_tap, cudaFuncAttributeMaxDynamicSharedMemorySize, SMEM_BYTES);

    __nv_bfloat16 *A1h, *A1l, *Bt1h, *Bt1l, *Bch, *Bcl, *k1h, *k1l;
    float *g;
    cudaGetSymbolAddress((void**)&A1h,  d_A1h);
    cudaGetSymbolAddress((void**)&A1l,  d_A1l);
    cudaGetSymbolAddress((void**)&Bt1h, d_Bt1h);
    cudaGetSymbolAddress((void**)&Bt1l, d_Bt1l);
    cudaGetSymbolAddress((void**)&Bch,  d_Bch);
    cudaGetSymbolAddress((void**)&Bcl,  d_Bcl);
    cudaGetSymbolAddress((void**)&k1h,  d_k1h);
    cudaGetSymbolAddress((void**)&k1l,  d_k1l);
    cudaGetSymbolAddress((void**)&g,    d_g);

    // side stream (captured fork/join): prep_Bc gates stage2; g/norms gate kernel_D
    cudaStream_t s2;
    cudaStreamCreateWithFlags(&s2, cudaStreamNonBlocking);
    cudaEvent_t ev0, ev2, ev3;
    cudaEventCreateWithFlags(&ev0, cudaEventDisableTiming);
    cudaEventCreateWithFlags(&ev2, cudaEventDisableTiming);
    cudaEventCreateWithFlags(&ev3, cudaEventDisableTiming);

    cudaEventRecord(ev0, 0);
    cudaStreamWaitEvent(s2, ev0, 0);
    prep_Bc<<<8192, 256, 0, s2>>>(wc);
    cudaEventRecord(ev2, s2);
    g_kernel<<<16384, 256, 0, s2>>>(feat, w_sp);
    norms_w<<<25, 256, 0, s2>>>(w_cls);
    cudaEventRecord(ev3, s2);

    // main branch: stage1 prep + stage1 GEMM (K-split 3: 288 units) + epi1
    prep_A1<<<2048, 256>>>(mem_feat);
    prep_Bt1<<<dim3(192, 64), 256>>>(wt);
    gemm_tap<<<dim3(144, 2), 512, SMEM_BYTES>>>(A1h, A1l, 2048, Bt1h, Bt1l, 0);
    epi1<<<1248, 256>>>(bt);

    // join prep_Bc before stage2
    cudaStreamWaitEvent(0, ev2, 0);
    // stage 2: 672 units (tap x kseg) -> fp32 partials
    gemm_tap<<<dim3(336, 2), 512, SMEM_BYTES>>>(k1h, k1l, 6144, Bch, Bcl, 1);

    // join g/norms before kernel_D
    cudaStreamWaitEvent(0, ev3, 0);
    kernel_D<<<dim3(7, 32), 256>>>(g, bc);
    reduce_D<<<64, 224>>>(b_sp);
    cos_kernel<<<1600, 256>>>(w_cls, label, out);

    (void)in_sizes; (void)n_in; (void)out_size;
}